// round 1
// baseline (speedup 1.0000x reference)
#include <cuda_runtime.h>

// EDMLoss: rec + 0.25 * memory_loss - 0.1 * mean(Dhat)
// Shapes: Xhat,X: [64,8,512]; H: [64,256,512]; M: [256,512]; Dhat: [64,512]
// Dominant work: nearest-codeword search == [32768 x 256] @ [256 x 512] GEMM
// with fused argmin epilogue.

namespace {
constexpr int Bn = 64, Dn = 256, Tn = 512, Kn = 512;
constexpr int N_REC  = 64 * 8 * 512;   // 262144
constexpr int N_DHAT = 64 * 512;       // 32768
constexpr int TT = 32;   // t-tile per block
constexpr int KT = 64;   // k-tile
constexpr int DC = 32;   // d-chunk for M streaming
}

__device__ double g_acc[3];            // 0: rec sum, 1: mem sum, 2: dhat sum
__device__ float  g_hnorm[Bn * Tn];
__device__ float  g_mnorm[Kn];

__global__ void k_init() {
    if (threadIdx.x < 3) g_acc[threadIdx.x] = 0.0;
}

// ||h||^2 per (b,t). Coalesced across t (stride-T over d).
__global__ void k_hnorm(const float* __restrict__ H) {
    int idx = blockIdx.x * 256 + threadIdx.x;     // b*T + t
    int b = idx >> 9, t = idx & 511;
    const float* p = H + (size_t)b * Dn * Tn + t;
    float s = 0.f;
    #pragma unroll 8
    for (int d = 0; d < Dn; ++d) { float v = p[(size_t)d * Tn]; s = fmaf(v, v, s); }
    g_hnorm[idx] = s;
}

// ||m||^2 per k. Coalesced across k.
__global__ void k_mnorm(const float* __restrict__ M) {
    int k = blockIdx.x * 256 + threadIdx.x;
    float s = 0.f;
    #pragma unroll 8
    for (int d = 0; d < Dn; ++d) { float v = M[(size_t)d * Kn + k]; s = fmaf(v, v, s); }
    g_mnorm[k] = s;
}

// WHICH==0: sum (a-b)^2 -> g_acc[0];  WHICH==2: sum a -> g_acc[2]
template <int WHICH>
__global__ void k_reduce(const float* __restrict__ a, const float* __restrict__ b, int n) {
    float s = 0.f;
    for (int i = blockIdx.x * blockDim.x + threadIdx.x; i < n; i += gridDim.x * blockDim.x) {
        if (WHICH == 0) { float d = a[i] - b[i]; s = fmaf(d, d, s); }
        else            { s += a[i]; }
    }
    #pragma unroll
    for (int o = 16; o; o >>= 1) s += __shfl_down_sync(0xffffffffu, s, o);
    __shared__ float ws[8];
    int lane = threadIdx.x & 31, w = threadIdx.x >> 5;
    if (!lane) ws[w] = s;
    __syncthreads();
    if (!w) {
        s = (lane < 8) ? ws[lane] : 0.f;
        #pragma unroll
        for (int o = 4; o; o >>= 1) s += __shfl_down_sync(0xffffffffu, s, o);
        if (!lane) atomicAdd(&g_acc[WHICH], (double)s);
    }
}

// Main fused GEMM + argmin kernel.
// Block: one (b, 32-t tile). H tile [256 x 32] resident in shared for whole block.
// Loop k in tiles of 64, streaming M chunks [32 x 64] through shared.
// Thread micro-tile: 2 t x 4 k (16x16 thread grid). 256 threads.
__global__ __launch_bounds__(256) void k_mem(const float* __restrict__ H,
                                             const float* __restrict__ M) {
    __shared__ float  Hs[Dn][TT];   // 32 KB
    __shared__ float  Ms[DC][KT];   // 8 KB
    __shared__ float  mns[Kn];      // 2 KB
    __shared__ double blk[16];

    const int tid = threadIdx.x;
    const int b   = blockIdx.y;
    const int t0  = blockIdx.x * TT;

    mns[tid]       = g_mnorm[tid];
    mns[tid + 256] = g_mnorm[tid + 256];

    // Load full H tile once: 256x32 floats, 32 per thread, coalesced 128B rows.
    const float* Hp = H + (size_t)b * Dn * Tn + t0;
    #pragma unroll
    for (int p = 0; p < (Dn * TT) / 256; ++p) {
        int idx = tid + p * 256;
        int dd = idx >> 5, tt = idx & 31;
        Hs[dd][tt] = Hp[(size_t)dd * Tn + tt];
    }
    __syncthreads();

    const int tx = tid & 15, ty = tid >> 4;
    const int tsub = ty * 2, ksub = tx * 4;

    float mn0 = 3.0e38f, mn1 = 3.0e38f;

    for (int k0 = 0; k0 < Kn; k0 += KT) {
        float acc[2][4];
        #pragma unroll
        for (int i = 0; i < 2; ++i)
            #pragma unroll
            for (int j = 0; j < 4; ++j) acc[i][j] = 0.f;

        for (int d0 = 0; d0 < Dn; d0 += DC) {
            __syncthreads();   // previous Ms consumers done
            #pragma unroll
            for (int p = 0; p < (DC * KT) / 256; ++p) {
                int idx = tid + p * 256;
                int dd = idx >> 6, kk = idx & 63;
                Ms[dd][kk] = M[(size_t)(d0 + dd) * Kn + k0 + kk];
            }
            __syncthreads();

            #pragma unroll
            for (int d = 0; d < DC; ++d) {
                float2 a  = *(const float2*)&Hs[d0 + d][tsub];
                float4 bb = *(const float4*)&Ms[d][ksub];
                acc[0][0] = fmaf(a.x, bb.x, acc[0][0]);
                acc[0][1] = fmaf(a.x, bb.y, acc[0][1]);
                acc[0][2] = fmaf(a.x, bb.z, acc[0][2]);
                acc[0][3] = fmaf(a.x, bb.w, acc[0][3]);
                acc[1][0] = fmaf(a.y, bb.x, acc[1][0]);
                acc[1][1] = fmaf(a.y, bb.y, acc[1][1]);
                acc[1][2] = fmaf(a.y, bb.z, acc[1][2]);
                acc[1][3] = fmaf(a.y, bb.w, acc[1][3]);
            }
        }

        // Epilogue: score = ||m||^2 - 2*dot; track running min (argmin-equivalent).
        #pragma unroll
        for (int j = 0; j < 4; ++j) {
            float m2 = mns[k0 + ksub + j];
            mn0 = fminf(mn0, fmaf(-2.f, acc[0][j], m2));
            mn1 = fminf(mn1, fmaf(-2.f, acc[1][j], m2));
        }
    }

    // Min-reduce across the 16 k-lanes sharing the same t pair (width-16 segments).
    #pragma unroll
    for (int o = 8; o; o >>= 1) {
        mn0 = fminf(mn0, __shfl_down_sync(0xffffffffu, mn0, o, 16));
        mn1 = fminf(mn1, __shfl_down_sync(0xffffffffu, mn1, o, 16));
    }

    if (tx == 0) {
        const float* hn = g_hnorm + b * Tn + t0 + tsub;
        // forward value of sg-loss = 2 * ||h - z||^2 = 2 * (||h||^2 + min score)
        blk[ty] = 2.0 * ((double)(hn[0] + mn0) + (double)(hn[1] + mn1));
    }
    __syncthreads();
    if (tid == 0) {
        double s = 0.0;
        #pragma unroll
        for (int i = 0; i < 16; ++i) s += blk[i];
        atomicAdd(&g_acc[1], s);
    }
}

__global__ void k_final(float* out) {
    out[0] = (float)(g_acc[0] / (double)N_REC
                     + 0.25 * g_acc[1] / (double)(Bn * Dn * Tn)
                     - 0.1 * g_acc[2] / (double)N_DHAT);
}

extern "C" void kernel_launch(void* const* d_in, const int* in_sizes, int n_in,
                              void* d_out, int out_size) {
    (void)in_sizes; (void)n_in; (void)out_size;
    const float* Xhat = (const float*)d_in[0];
    const float* X    = (const float*)d_in[1];
    const float* H    = (const float*)d_in[2];
    const float* M    = (const float*)d_in[3];
    const float* Dh   = (const float*)d_in[4];

    k_init<<<1, 32>>>();
    k_hnorm<<<(Bn * Tn) / 256, 256>>>(H);
    k_mnorm<<<Kn / 256, 256>>>(M);
    k_reduce<0><<<256, 256>>>(Xhat, X, N_REC);
    k_reduce<2><<<32, 256>>>(Dh, nullptr, N_DHAT);

    dim3 grid(Tn / TT, Bn);
    k_mem<<<grid, 256>>>(H, M);

    k_final<<<1, 1>>>((float*)d_out);
}

// round 3
// speedup vs baseline: 7.6200x; 7.6200x over previous
#include <cuda_runtime.h>
#include <cuda_bf16.h>
#include <cstdint>

// EDMLoss = mean((Xhat-X)^2) + 0.25*memloss - 0.1*mean(Dhat)
// memloss = 2*(sum||h||^2 + sum_row min_k(||m_k||^2 - 2 h.m_k)) / (B*D*T)
// GEMM [32768x256]@[256x512] via mma.sync bf16 (no sm_100a features needed).

namespace {
constexpr int Bn = 64, Dn = 256, Tn = 512, Kn = 512;
constexpr int N_REC  = 64 * 8 * 512;
constexpr int N_DHAT = 64 * 512;

// dynamic smem layout (bytes) for k_mma
constexpr uint32_t AP    = 272;                 // row pitch (128 bf16 + 8 pad)
constexpr uint32_t SA    = 0;                   // A: 256 rows * 272
constexpr uint32_t SB0   = 69632;               // B buf0: 256 * 272
constexpr uint32_t SB1   = 139264;              // B buf1
constexpr uint32_t SMNS  = 208896;              // 512 f32 ||m||^2
constexpr uint32_t SRMIN = 210944;              // 2 * 128 f32 row mins
constexpr uint32_t SRED  = 211968;              // 8 f32 hsq + pad + 4 doubles
constexpr uint32_t SMEMT = 212096;
}

__device__ double g_acc[4];      // 0 rec, 1 sum-minscore, 2 dhat, 3 sum H^2
__device__ float  g_mnorm[Kn];
__device__ __align__(16) __nv_bfloat16 g_Mc[(size_t)Dn * Kn];   // bf16 copy of M, [d][k]

__device__ __forceinline__ uint32_t smem_u32(const void* p) {
    uint32_t a;
    asm("{ .reg .u64 t; cvta.to.shared.u64 t, %1; cvt.u32.u64 %0, t; }" : "=r"(a) : "l"(p));
    return a;
}
__device__ __forceinline__ void ldsm4t(uint32_t* r, uint32_t addr) {
    asm volatile("ldmatrix.sync.aligned.m8n8.x4.trans.shared.b16 {%0,%1,%2,%3}, [%4];"
                 : "=r"(r[0]), "=r"(r[1]), "=r"(r[2]), "=r"(r[3]) : "r"(addr));
}
__device__ __forceinline__ void mma16816(float* c, const uint32_t* a, const uint32_t* b) {
    asm volatile("mma.sync.aligned.m16n8k16.row.col.f32.bf16.bf16.f32 "
                 "{%0,%1,%2,%3}, {%4,%5,%6,%7}, {%8,%9}, {%0,%1,%2,%3};"
                 : "+f"(c[0]), "+f"(c[1]), "+f"(c[2]), "+f"(c[3])
                 : "r"(a[0]), "r"(a[1]), "r"(a[2]), "r"(a[3]), "r"(b[0]), "r"(b[1]));
}

// ---- prep: zero accumulators, convert M to bf16, compute ||m_k||^2 ----
__global__ void k_prep(const float* __restrict__ M) {
    int k = blockIdx.x * 256 + threadIdx.x;        // grid 2 x 256 -> 512 columns
    if (blockIdx.x == 0 && threadIdx.x < 4) g_acc[threadIdx.x] = 0.0;
    float s = 0.f;
    #pragma unroll 8
    for (int d = 0; d < Dn; ++d) {
        float v = M[(size_t)d * Kn + k];
        g_Mc[(size_t)d * Kn + k] = __float2bfloat16(v);
        s = fmaf(v, v, s);
    }
    g_mnorm[k] = s;
}

// ---- tail: rec-loss + dhat reductions (one kernel, block ranges) ----
__global__ void k_tail(const float* __restrict__ Xhat, const float* __restrict__ X,
                       const float* __restrict__ Dh) {
    int which; const float* a; const float* b; int n; int blk0;
    if (blockIdx.x < 256) { which = 0; a = Xhat; b = X;   n = N_REC;  blk0 = 0;   }
    else                  { which = 2; a = Dh;   b = 0;   n = N_DHAT; blk0 = 256; }
    int nb = (which == 0) ? 256 : 32;
    float s = 0.f;
    for (int i = (blockIdx.x - blk0) * 256 + threadIdx.x; i < n; i += nb * 256) {
        if (which == 0) { float d = a[i] - b[i]; s = fmaf(d, d, s); }
        else            { s += a[i]; }
    }
    #pragma unroll
    for (int o = 16; o; o >>= 1) s += __shfl_down_sync(0xffffffffu, s, o);
    __shared__ float ws[8];
    int lane = threadIdx.x & 31, w = threadIdx.x >> 5;
    if (!lane) ws[w] = s;
    __syncthreads();
    if (threadIdx.x == 0) {
        float t = 0.f;
        #pragma unroll
        for (int i = 0; i < 8; ++i) t += ws[i];
        atomicAdd(&g_acc[which], (double)t);
    }
}

// ---- main GEMM + min-epilogue ----
// CTA: 128 rows x 512 cols. A = H tile bf16 [256 d][128 t] (ldmatrix.trans),
// B = g_Mc chunks [256 d][128 n] via cp.async double buffer.
__global__ __launch_bounds__(256, 1) void k_mma(const float* __restrict__ H) {
    extern __shared__ char sm[];
    const uint32_t sb = smem_u32(sm);
    const int tid = threadIdx.x, w = tid >> 5, ln = tid & 31;
    const int row0 = blockIdx.x * 128;
    const int b = row0 >> 9, t0 = row0 & 511;

    // ||m||^2 table to smem
    ((float*)(sm + SMNS))[tid]       = g_mnorm[tid];
    ((float*)(sm + SMNS))[tid + 256] = g_mnorm[tid + 256];

    // B chunk loader (cp.async, 16B x 16 per thread = 64KB)
    const size_t gmc = __cvta_generic_to_global((const void*)g_Mc);
    auto cp_chunk = [&](int c, uint32_t dstoff) {
        #pragma unroll
        for (int i = 0; i < 16; ++i) {
            int u = tid + 256 * i;                // 0..4095
            int d = u >> 4, seg = u & 15;
            uint32_t dst = sb + dstoff + d * AP + seg * 16;
            size_t   src = gmc + (size_t)d * 1024 + (size_t)c * 256 + seg * 16;
            asm volatile("cp.async.cg.shared.global [%0], [%1], 16;" :: "r"(dst), "l"(src));
        }
        asm volatile("cp.async.commit_group;" ::: "memory");
    };
    cp_chunk(0, SB0);

    // Stage A: H[b][d][t0..t0+127] fp32 -> bf16 smem [d][t]; accumulate sum(H^2).
    float sq = 0.f;
    const float* Hp = H + (size_t)b * Dn * Tn + t0;
    #pragma unroll
    for (int i = 0; i < 32; ++i) {
        int d = i * 8 + w;
        float4 v = *(const float4*)(Hp + (size_t)d * Tn + ln * 4);
        sq = fmaf(v.x, v.x, fmaf(v.y, v.y, fmaf(v.z, v.z, fmaf(v.w, v.w, sq))));
        __nv_bfloat162 p0 = __floats2bfloat162_rn(v.x, v.y);
        __nv_bfloat162 p1 = __floats2bfloat162_rn(v.z, v.w);
        uint32_t a = sb + SA + d * AP + ln * 8;
        asm volatile("st.shared.v2.b32 [%0], {%1,%2};"
                     :: "r"(a), "r"(*(uint32_t*)&p0), "r"(*(uint32_t*)&p1) : "memory");
    }
    #pragma unroll
    for (int o = 16; o; o >>= 1) sq += __shfl_down_sync(0xffffffffu, sq, o);
    if (!ln) ((float*)(sm + SRED))[w] = sq;

    const int wm = (w & 3) * 32;          // warp row base
    const int wn = (w >> 2) * 64;         // warp col base
    const int s1 = ((ln >> 3) & 1) * 8;   // matrix selector 1
    const int s2 = (ln >> 4) * 8;         // matrix selector 2
    const int r8 = ln & 7;
    const float* mns = (const float*)(sm + SMNS);

    float rm[4] = {3.4e38f, 3.4e38f, 3.4e38f, 3.4e38f};

    for (int c = 0; c < 4; ++c) {
        asm volatile("cp.async.wait_group 0;" ::: "memory");
        __syncthreads();                              // chunk c (and A on c==0) ready
        if (c < 3) cp_chunk(c + 1, (c & 1) ? SB0 : SB1);
        const uint32_t bb = sb + ((c & 1) ? SB1 : SB0);

        float acc[2][8][4];
        #pragma unroll
        for (int mf = 0; mf < 2; ++mf)
            #pragma unroll
            for (int nf = 0; nf < 8; ++nf)
                #pragma unroll
                for (int j = 0; j < 4; ++j) acc[mf][nf][j] = 0.f;

        #pragma unroll
        for (int ks = 0; ks < 16; ++ks) {
            const int d0 = ks * 16;
            uint32_t af[2][4], bf[4][4];
            #pragma unroll
            for (int mf = 0; mf < 2; ++mf)
                ldsm4t(af[mf], sb + SA + (d0 + s2 + r8) * AP + (wm + mf * 16 + s1) * 2);
            #pragma unroll
            for (int np = 0; np < 4; ++np)
                ldsm4t(bf[np], bb + (d0 + s1 + r8) * AP + (wn + np * 16 + s2) * 2);
            #pragma unroll
            for (int mf = 0; mf < 2; ++mf)
                #pragma unroll
                for (int nf = 0; nf < 8; ++nf)
                    mma16816(acc[mf][nf], af[mf], &bf[nf >> 1][(nf & 1) * 2]);
        }

        // epilogue: score = ||m||^2 - 2*dot, track per-row running min
        const int cb = c * 128 + wn + 2 * (ln & 3);
        #pragma unroll
        for (int nf = 0; nf < 8; ++nf) {
            float m0 = mns[cb + nf * 8], m1 = mns[cb + nf * 8 + 1];
            rm[0] = fminf(rm[0], fminf(fmaf(-2.f, acc[0][nf][0], m0), fmaf(-2.f, acc[0][nf][1], m1)));
            rm[1] = fminf(rm[1], fminf(fmaf(-2.f, acc[0][nf][2], m0), fmaf(-2.f, acc[0][nf][3], m1)));
            rm[2] = fminf(rm[2], fminf(fmaf(-2.f, acc[1][nf][0], m0), fmaf(-2.f, acc[1][nf][1], m1)));
            rm[3] = fminf(rm[3], fminf(fmaf(-2.f, acc[1][nf][2], m0), fmaf(-2.f, acc[1][nf][3], m1)));
        }
    }

    // combine the 4 lanes sharing each row
    #pragma unroll
    for (int o = 1; o < 4; o <<= 1) {
        #pragma unroll
        for (int i = 0; i < 4; ++i) rm[i] = fminf(rm[i], __shfl_xor_sync(0xffffffffu, rm[i], o));
    }
    if ((ln & 3) == 0) {
        float* rmin = (float*)(sm + SRMIN) + (w >> 2) * 128;
        int r = wm + (ln >> 2);
        rmin[r] = rm[0]; rmin[r + 8] = rm[1]; rmin[r + 16] = rm[2]; rmin[r + 24] = rm[3];
    }
    __syncthreads();

    if (tid < 128) {
        const float* r0 = (const float*)(sm + SRMIN);
        double s = (double)fminf(r0[tid], r0[tid + 128]);
        #pragma unroll
        for (int o = 16; o; o >>= 1) s += __shfl_down_sync(0xffffffffu, s, o);
        if (!ln) ((double*)(sm + SRED + 64))[w] = s;
    }
    __syncthreads();
    if (tid == 0) {
        const double* dr = (const double*)(sm + SRED + 64);
        atomicAdd(&g_acc[1], dr[0] + dr[1] + dr[2] + dr[3]);
        const float* ws = (const float*)(sm + SRED);
        double hs = 0.0;
        #pragma unroll
        for (int i = 0; i < 8; ++i) hs += (double)ws[i];
        atomicAdd(&g_acc[3], hs);
    }
}

__global__ void k_final(float* out) {
    double mem = 2.0 * (g_acc[3] + g_acc[1]) / (double)((size_t)Bn * Dn * Tn);
    out[0] = (float)(g_acc[0] / (double)N_REC + 0.25 * mem - 0.1 * g_acc[2] / (double)N_DHAT);
}

extern "C" void kernel_launch(void* const* d_in, const int* in_sizes, int n_in,
                              void* d_out, int out_size) {
    (void)in_sizes; (void)n_in; (void)out_size;
    const float* Xhat = (const float*)d_in[0];
    const float* X    = (const float*)d_in[1];
    const float* H    = (const float*)d_in[2];
    const float* M    = (const float*)d_in[3];
    const float* Dh   = (const float*)d_in[4];

    cudaFuncSetAttribute(k_mma, cudaFuncAttributeMaxDynamicSharedMemorySize, SMEMT);

    k_prep<<<2, 256>>>(M);
    k_mma<<<256, 256, SMEMT>>>(H);
    k_tail<<<288, 256>>>(Xhat, X, Dh);
    k_final<<<1, 1>>>((float*)d_out);
}

// round 4
// speedup vs baseline: 7.6250x; 1.0007x over previous
#include <cuda_runtime.h>
#include <cuda_bf16.h>
#include <cstdint>

// EDMLoss = mean((Xhat-X)^2) + 0.25*memloss - 0.1*mean(Dhat)
// memloss = 2*(sum||h||^2 + sum_row min_k(||m_k||^2 - 2 h.m_k)) / (B*D*T)
// GEMM [32768x256]@[256x512] via mma.sync bf16. Two launches total:
//   k_prep: M->bf16 + ||m||^2  (blocks 0-1), rec reduction (2-257), dhat (258-289)
//   k_mma : GEMM + fused min epilogue; last CTA (ticket) finalizes output.

namespace {
constexpr int Bn = 64, Dn = 256, Tn = 512, Kn = 512;
constexpr int N_REC  = 64 * 8 * 512;
constexpr int N_DHAT = 64 * 512;

constexpr uint32_t AP    = 272;                 // smem row pitch bytes (128 bf16 + pad)
constexpr uint32_t SA    = 0;                   // A tile: 256 * 272
constexpr uint32_t SB0   = 69632;               // B buf0: 256 * 272
constexpr uint32_t SB1   = 139264;              // B buf1
constexpr uint32_t SMNS  = 208896;              // 512 f32 ||m||^2
constexpr uint32_t SRMIN = 210944;              // 2*128 f32 row mins
constexpr uint32_t SRED  = 211968;              // 8 f32 + 4 doubles
constexpr uint32_t SMEMT = 212096;
}

__device__ double g_acc[4];      // 0 rec, 1 sum-minscore, 2 dhat, 3 sum H^2  (zero-invariant)
__device__ unsigned g_ticket;
__device__ float  g_mnorm[Kn];
__device__ __align__(16) __nv_bfloat16 g_Mc[(size_t)Dn * Kn];

__device__ __forceinline__ uint32_t smem_u32(const void* p) {
    uint32_t a;
    asm("{ .reg .u64 t; cvta.to.shared.u64 t, %1; cvt.u32.u64 %0, t; }" : "=r"(a) : "l"(p));
    return a;
}
__device__ __forceinline__ void ldsm4t(uint32_t* r, uint32_t addr) {
    asm volatile("ldmatrix.sync.aligned.m8n8.x4.trans.shared.b16 {%0,%1,%2,%3}, [%4];"
                 : "=r"(r[0]), "=r"(r[1]), "=r"(r[2]), "=r"(r[3]) : "r"(addr));
}
__device__ __forceinline__ void mma16816(float* c, const uint32_t* a, const uint32_t* b) {
    asm volatile("mma.sync.aligned.m16n8k16.row.col.f32.bf16.bf16.f32 "
                 "{%0,%1,%2,%3}, {%4,%5,%6,%7}, {%8,%9}, {%0,%1,%2,%3};"
                 : "+f"(c[0]), "+f"(c[1]), "+f"(c[2]), "+f"(c[3])
                 : "r"(a[0]), "r"(a[1]), "r"(a[2]), "r"(a[3]), "r"(b[0]), "r"(b[1]));
}

// ---- prep: M convert + mnorm, plus rec/dhat flat reductions (one wide grid) ----
__global__ __launch_bounds__(256) void k_prep(const float* __restrict__ M,
                                              const float* __restrict__ Xhat,
                                              const float* __restrict__ X,
                                              const float* __restrict__ Dh) {
    const int blk = blockIdx.x;
    if (blk < 2) {
        int k = blk * 256 + threadIdx.x;
        float s = 0.f;
        #pragma unroll 8
        for (int d = 0; d < Dn; ++d) {
            float v = M[(size_t)d * Kn + k];
            g_Mc[(size_t)d * Kn + k] = __float2bfloat16(v);
            s = fmaf(v, v, s);
        }
        g_mnorm[k] = s;
        return;
    }
    int which, n, b0, nb;
    const float* a; const float* bp;
    if (blk < 258) { which = 0; a = Xhat; bp = X; n = N_REC;  b0 = 2;   nb = 256; }
    else           { which = 2; a = Dh;   bp = 0; n = N_DHAT; b0 = 258; nb = 32;  }
    float s = 0.f;
    for (int i = (blk - b0) * 256 + threadIdx.x; i < n; i += nb * 256) {
        if (which == 0) { float d = a[i] - bp[i]; s = fmaf(d, d, s); }
        else            { s += a[i]; }
    }
    #pragma unroll
    for (int o = 16; o; o >>= 1) s += __shfl_down_sync(0xffffffffu, s, o);
    __shared__ float ws[8];
    int lane = threadIdx.x & 31, w = threadIdx.x >> 5;
    if (!lane) ws[w] = s;
    __syncthreads();
    if (threadIdx.x == 0) {
        float t = 0.f;
        #pragma unroll
        for (int i = 0; i < 8; ++i) t += ws[i];
        atomicAdd(&g_acc[which], (double)t);
    }
}

// ---- main GEMM + min epilogue + ticketed finalization ----
__global__ __launch_bounds__(256, 1) void k_mma(const float* __restrict__ H, float* out) {
    extern __shared__ char sm[];
    const uint32_t sb = smem_u32(sm);
    const int tid = threadIdx.x, w = tid >> 5, ln = tid & 31;
    const int row0 = blockIdx.x * 128;
    const int b = row0 >> 9, t0 = row0 & 511;

    ((float*)(sm + SMNS))[tid]       = g_mnorm[tid];
    ((float*)(sm + SMNS))[tid + 256] = g_mnorm[tid + 256];

    const size_t gmc = __cvta_generic_to_global((const void*)g_Mc);
    auto cp_chunk = [&](int c, uint32_t dstoff) {
        #pragma unroll
        for (int i = 0; i < 16; ++i) {
            int u = tid + 256 * i;
            int d = u >> 4, seg = u & 15;
            uint32_t dst = sb + dstoff + d * AP + seg * 16;
            size_t   src = gmc + (size_t)d * 1024 + (size_t)c * 256 + seg * 16;
            asm volatile("cp.async.cg.shared.global [%0], [%1], 16;" :: "r"(dst), "l"(src));
        }
        asm volatile("cp.async.commit_group;" ::: "memory");
    };
    cp_chunk(0, SB0);

    // Stage A: H[b][d][t0..t0+127] fp32 -> bf16 smem [d][t]; accumulate sum(H^2).
    float sq = 0.f;
    const float* Hp = H + (size_t)b * Dn * Tn + t0;
    #pragma unroll
    for (int i = 0; i < 32; ++i) {
        int d = i * 8 + w;
        float4 v = *(const float4*)(Hp + (size_t)d * Tn + ln * 4);
        sq = fmaf(v.x, v.x, fmaf(v.y, v.y, fmaf(v.z, v.z, fmaf(v.w, v.w, sq))));
        __nv_bfloat162 p0 = __floats2bfloat162_rn(v.x, v.y);
        __nv_bfloat162 p1 = __floats2bfloat162_rn(v.z, v.w);
        uint32_t a = sb + SA + d * AP + ln * 8;
        asm volatile("st.shared.v2.b32 [%0], {%1,%2};"
                     :: "r"(a), "r"(*(uint32_t*)&p0), "r"(*(uint32_t*)&p1) : "memory");
    }
    #pragma unroll
    for (int o = 16; o; o >>= 1) sq += __shfl_down_sync(0xffffffffu, sq, o);
    if (!ln) ((float*)(sm + SRED))[w] = sq;

    const int wm = (w & 3) * 32;
    const int wn = (w >> 2) * 64;
    const int s1 = ((ln >> 3) & 1) * 8;
    const int s2 = (ln >> 4) * 8;
    const int r8 = ln & 7;
    const float* mns = (const float*)(sm + SMNS);

    float rm[4] = {3.4e38f, 3.4e38f, 3.4e38f, 3.4e38f};

    for (int c = 0; c < 4; ++c) {
        asm volatile("cp.async.wait_group 0;" ::: "memory");
        __syncthreads();
        if (c < 3) cp_chunk(c + 1, (c & 1) ? SB0 : SB1);
        const uint32_t bb = sb + ((c & 1) ? SB1 : SB0);

        float acc[2][8][4];
        #pragma unroll
        for (int mf = 0; mf < 2; ++mf)
            #pragma unroll
            for (int nf = 0; nf < 8; ++nf)
                #pragma unroll
                for (int j = 0; j < 4; ++j) acc[mf][nf][j] = 0.f;

        #pragma unroll
        for (int ks = 0; ks < 16; ++ks) {
            const int d0 = ks * 16;
            uint32_t af[2][4], bf[4][4];
            #pragma unroll
            for (int mf = 0; mf < 2; ++mf)
                ldsm4t(af[mf], sb + SA + (d0 + s2 + r8) * AP + (wm + mf * 16 + s1) * 2);
            #pragma unroll
            for (int np = 0; np < 4; ++np)
                ldsm4t(bf[np], bb + (d0 + s1 + r8) * AP + (wn + np * 16 + s2) * 2);
            #pragma unroll
            for (int mf = 0; mf < 2; ++mf)
                #pragma unroll
                for (int nf = 0; nf < 8; ++nf)
                    mma16816(acc[mf][nf], af[mf], &bf[nf >> 1][(nf & 1) * 2]);
        }

        const int cb = c * 128 + wn + 2 * (ln & 3);
        #pragma unroll
        for (int nf = 0; nf < 8; ++nf) {
            float m0 = mns[cb + nf * 8], m1 = mns[cb + nf * 8 + 1];
            rm[0] = fminf(rm[0], fminf(fmaf(-2.f, acc[0][nf][0], m0), fmaf(-2.f, acc[0][nf][1], m1)));
            rm[1] = fminf(rm[1], fminf(fmaf(-2.f, acc[0][nf][2], m0), fmaf(-2.f, acc[0][nf][3], m1)));
            rm[2] = fminf(rm[2], fminf(fmaf(-2.f, acc[1][nf][0], m0), fmaf(-2.f, acc[1][nf][1], m1)));
            rm[3] = fminf(rm[3], fminf(fmaf(-2.f, acc[1][nf][2], m0), fmaf(-2.f, acc[1][nf][3], m1)));
        }
    }

    #pragma unroll
    for (int o = 1; o < 4; o <<= 1) {
        #pragma unroll
        for (int i = 0; i < 4; ++i) rm[i] = fminf(rm[i], __shfl_xor_sync(0xffffffffu, rm[i], o));
    }
    if ((ln & 3) == 0) {
        float* rmin = (float*)(sm + SRMIN) + (w >> 2) * 128;
        int r = wm + (ln >> 2);
        rmin[r] = rm[0]; rmin[r + 8] = rm[1]; rmin[r + 16] = rm[2]; rmin[r + 24] = rm[3];
    }
    __syncthreads();

    if (tid < 128) {
        const float* r0 = (const float*)(sm + SRMIN);
        double s = (double)fminf(r0[tid], r0[tid + 128]);
        #pragma unroll
        for (int o = 16; o; o >>= 1) s += __shfl_down_sync(0xffffffffu, s, o);
        if (!ln) ((double*)(sm + SRED + 64))[w] = s;
    }
    __syncthreads();

    if (tid == 0) {
        const double* dr = (const double*)(sm + SRED + 64);
        atomicAdd(&g_acc[1], dr[0] + dr[1] + dr[2] + dr[3]);
        const float* ws = (const float*)(sm + SRED);
        double hs = 0.0;
        #pragma unroll
        for (int i = 0; i < 8; ++i) hs += (double)ws[i];
        atomicAdd(&g_acc[3], hs);

        __threadfence();
        unsigned old = atomicAdd(&g_ticket, 1u);
        if (old == gridDim.x - 1) {                  // last CTA: finalize + reset
            __threadfence();
            double a0 = *(volatile double*)&g_acc[0];
            double a1 = *(volatile double*)&g_acc[1];
            double a2 = *(volatile double*)&g_acc[2];
            double a3 = *(volatile double*)&g_acc[3];
            double mem = 2.0 * (a3 + a1) / (double)((size_t)Bn * Dn * Tn);
            out[0] = (float)(a0 / (double)N_REC + 0.25 * mem - 0.1 * a2 / (double)N_DHAT);
            g_acc[0] = 0.0; g_acc[1] = 0.0; g_acc[2] = 0.0; g_acc[3] = 0.0;
            g_ticket = 0u;
            __threadfence();
        }
    }
}

extern "C" void kernel_launch(void* const* d_in, const int* in_sizes, int n_in,
                              void* d_out, int out_size) {
    (void)in_sizes; (void)n_in; (void)out_size;
    const float* Xhat = (const float*)d_in[0];
    const float* X    = (const float*)d_in[1];
    const float* H    = (const float*)d_in[2];
    const float* M    = (const float*)d_in[3];
    const float* Dh   = (const float*)d_in[4];

    cudaFuncSetAttribute(k_mma, cudaFuncAttributeMaxDynamicSharedMemorySize, SMEMT);

    k_prep<<<290, 256>>>(M, Xhat, X, Dh);
    k_mma<<<256, 256, SMEMT>>>(H, (float*)d_out);
}

// round 5
// speedup vs baseline: 7.8184x; 1.0254x over previous
#include <cuda_runtime.h>
#include <cuda_bf16.h>
#include <cstdint>

// EDMLoss = mean((Xhat-X)^2) + 0.25*memloss - 0.1*mean(Dhat)
// memloss = 2*(sum||h||^2 + sum_row min_k(||m_k||^2 - 2 h.m_k)) / (B*D*T)
// GEMM [32768x256]@[256x512] via mma.sync bf16, 512-thread CTAs (16 warps).

namespace {
constexpr int Bn = 64, Dn = 256, Tn = 512, Kn = 512;
constexpr int N_REC  = 64 * 8 * 512;
constexpr int N_DHAT = 64 * 512;

constexpr uint32_t AP    = 272;                 // smem row pitch bytes (128 bf16 + pad)
constexpr uint32_t SA    = 0;                   // A tile: 256*272
constexpr uint32_t SB0   = 69632;               // B buf0
constexpr uint32_t SB1   = 139264;              // B buf1
constexpr uint32_t SMNS  = 208896;              // 512 f32 ||m||^2
constexpr uint32_t SRMIN = 210944;              // 4*128 f32 row mins
constexpr uint32_t SRED  = 212992;              // 16 f32 + pad + 4 doubles
constexpr uint32_t SMEMT = 213120;
}

__device__ double g_acc[4];      // 0 rec, 1 minscore, 2 dhat, 3 sum H^2 (zero-invariant)
__device__ unsigned g_ticket;
__device__ float  g_mnorm[Kn];
__device__ __align__(16) __nv_bfloat16 g_Mc[(size_t)Dn * Kn];

__device__ __forceinline__ uint32_t smem_u32(const void* p) {
    uint32_t a;
    asm("{ .reg .u64 t; cvta.to.shared.u64 t, %1; cvt.u32.u64 %0, t; }" : "=r"(a) : "l"(p));
    return a;
}
__device__ __forceinline__ void ldsm4t(uint32_t* r, uint32_t addr) {
    asm volatile("ldmatrix.sync.aligned.m8n8.x4.trans.shared.b16 {%0,%1,%2,%3}, [%4];"
                 : "=r"(r[0]), "=r"(r[1]), "=r"(r[2]), "=r"(r[3]) : "r"(addr));
}
__device__ __forceinline__ void mma16816(float* c, const uint32_t* a, const uint32_t* b) {
    asm volatile("mma.sync.aligned.m16n8k16.row.col.f32.bf16.bf16.f32 "
                 "{%0,%1,%2,%3}, {%4,%5,%6,%7}, {%8,%9}, {%0,%1,%2,%3};"
                 : "+f"(c[0]), "+f"(c[1]), "+f"(c[2]), "+f"(c[3])
                 : "r"(a[0]), "r"(a[1]), "r"(a[2]), "r"(a[3]), "r"(b[0]), "r"(b[1]));
}

// ---- prep: M convert + mnorm (blocks 0-1), rec (2-257), dhat (258-289) ----
__global__ __launch_bounds__(256) void k_prep(const float* __restrict__ M,
                                              const float* __restrict__ Xhat,
                                              const float* __restrict__ X,
                                              const float* __restrict__ Dh) {
    const int blk = blockIdx.x;
    if (blk < 2) {
        int k = blk * 256 + threadIdx.x;
        float s = 0.f;
        #pragma unroll 8
        for (int d = 0; d < Dn; ++d) {
            float v = M[(size_t)d * Kn + k];
            g_Mc[(size_t)d * Kn + k] = __float2bfloat16(v);
            s = fmaf(v, v, s);
        }
        g_mnorm[k] = s;
        return;
    }
    int which, n, b0, nb;
    const float* a; const float* bp;
    if (blk < 258) { which = 0; a = Xhat; bp = X; n = N_REC;  b0 = 2;   nb = 256; }
    else           { which = 2; a = Dh;   bp = 0; n = N_DHAT; b0 = 258; nb = 32;  }
    float s = 0.f;
    for (int i = (blk - b0) * 256 + threadIdx.x; i < n; i += nb * 256) {
        if (which == 0) { float d = a[i] - bp[i]; s = fmaf(d, d, s); }
        else            { s += a[i]; }
    }
    #pragma unroll
    for (int o = 16; o; o >>= 1) s += __shfl_down_sync(0xffffffffu, s, o);
    __shared__ float ws[8];
    int lane = threadIdx.x & 31, w = threadIdx.x >> 5;
    if (!lane) ws[w] = s;
    __syncthreads();
    if (threadIdx.x == 0) {
        float t = 0.f;
        #pragma unroll
        for (int i = 0; i < 8; ++i) t += ws[i];
        atomicAdd(&g_acc[which], (double)t);
    }
}

// ---- main GEMM + min epilogue, 512 threads ----
__global__ __launch_bounds__(512, 1) void k_mma(const float* __restrict__ H, float* out) {
    extern __shared__ char sm[];
    const uint32_t sb = smem_u32(sm);
    const int tid = threadIdx.x, w = tid >> 5, ln = tid & 31;
    const int row0 = blockIdx.x * 128;
    const int b = row0 >> 9, t0 = row0 & 511;

    ((float*)(sm + SMNS))[tid] = g_mnorm[tid];

    const size_t gmc = __cvta_generic_to_global((const void*)g_Mc);
    auto cp_chunk = [&](int c, uint32_t dstoff) {
        #pragma unroll
        for (int i = 0; i < 8; ++i) {
            int u = tid + 512 * i;                 // 0..4095 16B units
            int d = u >> 4, seg = u & 15;
            uint32_t dst = sb + dstoff + d * AP + seg * 16;
            size_t   src = gmc + (size_t)d * 1024 + (size_t)c * 256 + seg * 16;
            asm volatile("cp.async.cg.shared.global [%0], [%1], 16;" :: "r"(dst), "l"(src));
        }
        asm volatile("cp.async.commit_group;" ::: "memory");
    };
    cp_chunk(0, SB0);

    // Stage A: H[b][d][t0..t0+127] fp32 -> bf16 smem [d][t]; accumulate sum(H^2).
    float sq = 0.f;
    const float* Hp = H + (size_t)b * Dn * Tn + t0;
    #pragma unroll
    for (int i = 0; i < 16; ++i) {
        int d = i * 16 + w;
        float4 v = *(const float4*)(Hp + (size_t)d * Tn + ln * 4);
        sq = fmaf(v.x, v.x, fmaf(v.y, v.y, fmaf(v.z, v.z, fmaf(v.w, v.w, sq))));
        __nv_bfloat162 p0 = __floats2bfloat162_rn(v.x, v.y);
        __nv_bfloat162 p1 = __floats2bfloat162_rn(v.z, v.w);
        uint32_t a = sb + SA + d * AP + ln * 8;
        asm volatile("st.shared.v2.b32 [%0], {%1,%2};"
                     :: "r"(a), "r"(*(uint32_t*)&p0), "r"(*(uint32_t*)&p1) : "memory");
    }
    #pragma unroll
    for (int o = 16; o; o >>= 1) sq += __shfl_down_sync(0xffffffffu, sq, o);
    if (!ln) ((float*)(sm + SRED))[w] = sq;

    // 16 warps: 4 (m) x 4 (n). Warp tile per chunk: 32 rows x 32 cols.
    const int wm  = (w & 3) * 32;         // row base
    const int wn  = (w >> 2) * 32;        // col base within 128-col chunk
    const int s1  = ((ln >> 3) & 1) * 8;
    const int s2  = (ln >> 4) * 8;
    const int r8  = ln & 7;
    const float* mns = (const float*)(sm + SMNS);

    float rm[4] = {3.4e38f, 3.4e38f, 3.4e38f, 3.4e38f};

    for (int c = 0; c < 4; ++c) {
        asm volatile("cp.async.wait_group 0;" ::: "memory");
        __syncthreads();
        if (c < 3) cp_chunk(c + 1, (c & 1) ? SB0 : SB1);
        const uint32_t bb = sb + ((c & 1) ? SB1 : SB0);

        float acc[2][4][4];
        #pragma unroll
        for (int mf = 0; mf < 2; ++mf)
            #pragma unroll
            for (int nf = 0; nf < 4; ++nf)
                #pragma unroll
                for (int j = 0; j < 4; ++j) acc[mf][nf][j] = 0.f;

        #pragma unroll
        for (int ks = 0; ks < 16; ++ks) {
            const int d0 = ks * 16;
            uint32_t af[2][4], bf[2][4];
            #pragma unroll
            for (int mf = 0; mf < 2; ++mf)
                ldsm4t(af[mf], sb + SA + (d0 + s2 + r8) * AP + (wm + mf * 16 + s1) * 2);
            #pragma unroll
            for (int np = 0; np < 2; ++np)
                ldsm4t(bf[np], bb + (d0 + s1 + r8) * AP + (wn + np * 16 + s2) * 2);
            #pragma unroll
            for (int mf = 0; mf < 2; ++mf)
                #pragma unroll
                for (int nf = 0; nf < 4; ++nf)
                    mma16816(acc[mf][nf], af[mf], &bf[nf >> 1][(nf & 1) * 2]);
        }

        const int cb = c * 128 + wn + 2 * (ln & 3);
        #pragma unroll
        for (int nf = 0; nf < 4; ++nf) {
            float m0 = mns[cb + nf * 8], m1 = mns[cb + nf * 8 + 1];
            rm[0] = fminf(rm[0], fminf(fmaf(-2.f, acc[0][nf][0], m0), fmaf(-2.f, acc[0][nf][1], m1)));
            rm[1] = fminf(rm[1], fminf(fmaf(-2.f, acc[0][nf][2], m0), fmaf(-2.f, acc[0][nf][3], m1)));
            rm[2] = fminf(rm[2], fminf(fmaf(-2.f, acc[1][nf][0], m0), fmaf(-2.f, acc[1][nf][1], m1)));
            rm[3] = fminf(rm[3], fminf(fmaf(-2.f, acc[1][nf][2], m0), fmaf(-2.f, acc[1][nf][3], m1)));
        }
    }

    // combine 4 lanes sharing each row
    #pragma unroll
    for (int o = 1; o < 4; o <<= 1) {
        #pragma unroll
        for (int i = 0; i < 4; ++i) rm[i] = fminf(rm[i], __shfl_xor_sync(0xffffffffu, rm[i], o));
    }
    if ((ln & 3) == 0) {
        float* rmin = (float*)(sm + SRMIN) + (w >> 2) * 128;   // per n-warp-group array
        int r = wm + (ln >> 2);
        rmin[r] = rm[0]; rmin[r + 8] = rm[1]; rmin[r + 16] = rm[2]; rmin[r + 24] = rm[3];
    }
    __syncthreads();

    if (tid < 128) {
        const float* r0 = (const float*)(sm + SRMIN);
        float mv = fminf(fminf(r0[tid], r0[tid + 128]), fminf(r0[tid + 256], r0[tid + 384]));
        double s = (double)mv;
        #pragma unroll
        for (int o = 16; o; o >>= 1) s += __shfl_down_sync(0xffffffffu, s, o);
        if (!ln) ((double*)(sm + SRED + 64))[w] = s;
    }
    __syncthreads();

    if (tid == 0) {
        const double* dr = (const double*)(sm + SRED + 64);
        atomicAdd(&g_acc[1], dr[0] + dr[1] + dr[2] + dr[3]);
        const float* ws = (const float*)(sm + SRED);
        double hs = 0.0;
        #pragma unroll
        for (int i = 0; i < 16; ++i) hs += (double)ws[i];
        atomicAdd(&g_acc[3], hs);

        __threadfence();
        unsigned old = atomicAdd(&g_ticket, 1u);
        if (old == gridDim.x - 1) {
            __threadfence();
            double a0 = *(volatile double*)&g_acc[0];
            double a1 = *(volatile double*)&g_acc[1];
            double a2 = *(volatile double*)&g_acc[2];
            double a3 = *(volatile double*)&g_acc[3];
            double mem = 2.0 * (a3 + a1) / (double)((size_t)Bn * Dn * Tn);
            out[0] = (float)(a0 / (double)N_REC + 0.25 * mem - 0.1 * a2 / (double)N_DHAT);
            g_acc[0] = 0.0; g_acc[1] = 0.0; g_acc[2] = 0.0; g_acc[3] = 0.0;
            g_ticket = 0u;
            __threadfence();
        }
    }
}

extern "C" void kernel_launch(void* const* d_in, const int* in_sizes, int n_in,
                              void* d_out, int out_size) {
    (void)in_sizes; (void)n_in; (void)out_size;
    const float* Xhat = (const float*)d_in[0];
    const float* X    = (const float*)d_in[1];
    const float* H    = (const float*)d_in[2];
    const float* M    = (const float*)d_in[3];
    const float* Dh   = (const float*)d_in[4];

    cudaFuncSetAttribute(k_mma, cudaFuncAttributeMaxDynamicSharedMemorySize, SMEMT);

    k_prep<<<290, 256>>>(M, Xhat, X, Dh);
    k_mma<<<256, 512, SMEMT>>>(H, (float*)d_out);
}

// round 6
// speedup vs baseline: 8.3241x; 1.0647x over previous
#include <cuda_runtime.h>
#include <cuda_bf16.h>
#include <cstdint>

// EDMLoss = mean((Xhat-X)^2) + 0.25*memloss - 0.1*mean(Dhat)
// memloss = 2*(sum||h||^2 + sum_row min_k(||m_k||^2 - 2 h.m_k)) / (B*D*T)
// GEMM [32768x256]@[256x512] via mma.sync bf16.
// 128 CTAs (0.86 waves) x 512 threads; CTA tile 256 rows x 512 cols.

namespace {
constexpr int Bn = 64, Dn = 256, Tn = 512, Kn = 512;
constexpr int N_REC  = 64 * 8 * 512;
constexpr int N_DHAT = 64 * 512;

constexpr uint32_t AP    = 528;                 // A pitch bytes (256 bf16 + 16 pad)
constexpr uint32_t BP    = 144;                 // B pitch bytes (64 bf16 + 16 pad)
constexpr uint32_t SA    = 0;                   // A: 256*528 = 135168
constexpr uint32_t SB0   = 135168;              // B buf0: 256*144 = 36864
constexpr uint32_t SB1   = 172032;              // B buf1
constexpr uint32_t SMNS  = 208896;              // 512 f32 ||m||^2
constexpr uint32_t SRMIN = 210944;              // 2 groups * 256 f32 row mins
constexpr uint32_t SRED  = 212992;              // 16 f32 | 8 doubles
constexpr uint32_t SMEMT = 213120;
}

__device__ double g_acc[4];      // 0 rec, 1 minscore, 2 dhat, 3 sum H^2 (zero-invariant)
__device__ unsigned g_ticket;
__device__ float  g_mnorm[Kn];
__device__ __align__(16) __nv_bfloat16 g_Mc[(size_t)Dn * Kn];

__device__ __forceinline__ uint32_t smem_u32(const void* p) {
    uint32_t a;
    asm("{ .reg .u64 t; cvta.to.shared.u64 t, %1; cvt.u32.u64 %0, t; }" : "=r"(a) : "l"(p));
    return a;
}
__device__ __forceinline__ void ldsm4t(uint32_t* r, uint32_t addr) {
    asm volatile("ldmatrix.sync.aligned.m8n8.x4.trans.shared.b16 {%0,%1,%2,%3}, [%4];"
                 : "=r"(r[0]), "=r"(r[1]), "=r"(r[2]), "=r"(r[3]) : "r"(addr));
}
__device__ __forceinline__ void mma16816(float* c, const uint32_t* a, const uint32_t* b) {
    asm volatile("mma.sync.aligned.m16n8k16.row.col.f32.bf16.bf16.f32 "
                 "{%0,%1,%2,%3}, {%4,%5,%6,%7}, {%8,%9}, {%0,%1,%2,%3};"
                 : "+f"(c[0]), "+f"(c[1]), "+f"(c[2]), "+f"(c[3])
                 : "r"(a[0]), "r"(a[1]), "r"(a[2]), "r"(a[3]), "r"(b[0]), "r"(b[1]));
}

// ---- prep: M convert + mnorm (blocks 0-1), rec (2-257), dhat (258-289) ----
__global__ __launch_bounds__(256) void k_prep(const float* __restrict__ M,
                                              const float* __restrict__ Xhat,
                                              const float* __restrict__ X,
                                              const float* __restrict__ Dh) {
    const int blk = blockIdx.x;
    if (blk < 2) {
        int k = blk * 256 + threadIdx.x;
        float s = 0.f;
        #pragma unroll 8
        for (int d = 0; d < Dn; ++d) {
            float v = M[(size_t)d * Kn + k];
            g_Mc[(size_t)d * Kn + k] = __float2bfloat16(v);
            s = fmaf(v, v, s);
        }
        g_mnorm[k] = s;
        return;
    }
    int which, n, b0, nb;
    const float* a; const float* bp;
    if (blk < 258) { which = 0; a = Xhat; bp = X; n = N_REC;  b0 = 2;   nb = 256; }
    else           { which = 2; a = Dh;   bp = 0; n = N_DHAT; b0 = 258; nb = 32;  }
    float s = 0.f;
    for (int i = (blk - b0) * 256 + threadIdx.x; i < n; i += nb * 256) {
        if (which == 0) { float d = a[i] - bp[i]; s = fmaf(d, d, s); }
        else            { s += a[i]; }
    }
    #pragma unroll
    for (int o = 16; o; o >>= 1) s += __shfl_down_sync(0xffffffffu, s, o);
    __shared__ float ws[8];
    int lane = threadIdx.x & 31, w = threadIdx.x >> 5;
    if (!lane) ws[w] = s;
    __syncthreads();
    if (threadIdx.x == 0) {
        float t = 0.f;
        #pragma unroll
        for (int i = 0; i < 8; ++i) t += ws[i];
        atomicAdd(&g_acc[which], (double)t);
    }
}

// ---- main GEMM + min epilogue: 256 rows x 512 cols per CTA, 512 threads ----
__global__ __launch_bounds__(512, 1) void k_mma(const float* __restrict__ H, float* out) {
    extern __shared__ char sm[];
    const uint32_t sb = smem_u32(sm);
    const int tid = threadIdx.x, w = tid >> 5, ln = tid & 31;
    const int row0 = blockIdx.x * 256;
    const int b = row0 >> 9, t0 = row0 & 511;          // t0 in {0, 256}

    ((float*)(sm + SMNS))[tid] = g_mnorm[tid];

    const size_t gmc = __cvta_generic_to_global((const void*)g_Mc);
    auto cp_chunk = [&](int c, uint32_t dstoff) {       // 64-col chunk: 256 rows * 128B
        #pragma unroll
        for (int i = 0; i < 4; ++i) {
            int u = tid + 512 * i;                      // 0..2047 16B units
            int d = u >> 3, seg = u & 7;
            uint32_t dst = sb + dstoff + d * BP + seg * 16;
            size_t   src = gmc + (size_t)d * 1024 + (size_t)c * 128 + seg * 16;
            asm volatile("cp.async.cg.shared.global [%0], [%1], 16;" :: "r"(dst), "l"(src));
        }
        asm volatile("cp.async.commit_group;" ::: "memory");
    };
    cp_chunk(0, SB0);
    cp_chunk(1, SB1);

    // Stage A: H[b][d][t0..t0+255] fp32 -> bf16 smem [d][t]; accumulate sum(H^2).
    float sq = 0.f;
    const float* Hp = H + (size_t)b * Dn * Tn + t0;
    #pragma unroll
    for (int i = 0; i < 16; ++i) {
        int d = i * 16 + w;
        #pragma unroll
        for (int h = 0; h < 2; ++h) {
            int t = h * 128 + ln * 4;
            float4 v = *(const float4*)(Hp + (size_t)d * Tn + t);
            sq = fmaf(v.x, v.x, fmaf(v.y, v.y, fmaf(v.z, v.z, fmaf(v.w, v.w, sq))));
            __nv_bfloat162 p0 = __floats2bfloat162_rn(v.x, v.y);
            __nv_bfloat162 p1 = __floats2bfloat162_rn(v.z, v.w);
            uint32_t a = sb + SA + d * AP + t * 2;
            asm volatile("st.shared.v2.b32 [%0], {%1,%2};"
                         :: "r"(a), "r"(*(uint32_t*)&p0), "r"(*(uint32_t*)&p1) : "memory");
        }
    }
    #pragma unroll
    for (int o = 16; o; o >>= 1) sq += __shfl_down_sync(0xffffffffu, sq, o);
    if (!ln) ((float*)(sm + SRED))[w] = sq;

    // 16 warps: 8 (m) x 2 (n). Warp tile per chunk: 32 rows x 32 cols.
    const int wm  = (w & 7) * 32;
    const int wn  = (w >> 3) * 32;
    const int s1  = ((ln >> 3) & 1) * 8;
    const int s2  = (ln >> 4) * 8;
    const int r8  = ln & 7;
    const float* mns = (const float*)(sm + SMNS);

    float rm[4] = {3.4e38f, 3.4e38f, 3.4e38f, 3.4e38f};

    for (int c = 0; c < 8; ++c) {
        asm volatile("cp.async.wait_group 1;" ::: "memory");   // chunk c resident
        __syncthreads();
        const uint32_t bb = sb + ((c & 1) ? SB1 : SB0);

        float acc[2][4][4];
        #pragma unroll
        for (int mf = 0; mf < 2; ++mf)
            #pragma unroll
            for (int nf = 0; nf < 4; ++nf)
                #pragma unroll
                for (int j = 0; j < 4; ++j) acc[mf][nf][j] = 0.f;

        #pragma unroll
        for (int ks = 0; ks < 16; ++ks) {
            const int d0 = ks * 16;
            uint32_t af[2][4], bf[2][4];
            #pragma unroll
            for (int mf = 0; mf < 2; ++mf)
                ldsm4t(af[mf], sb + SA + (d0 + s2 + r8) * AP + (wm + mf * 16 + s1) * 2);
            #pragma unroll
            for (int np = 0; np < 2; ++np)
                ldsm4t(bf[np], bb + (d0 + s1 + r8) * BP + (wn + np * 16 + s2) * 2);
            #pragma unroll
            for (int mf = 0; mf < 2; ++mf)
                #pragma unroll
                for (int nf = 0; nf < 4; ++nf)
                    mma16816(acc[mf][nf], af[mf], &bf[nf >> 1][(nf & 1) * 2]);
        }

        // epilogue for this chunk, then release the buffer and prefetch c+2
        const int cb = c * 64 + wn + 2 * (ln & 3);
        #pragma unroll
        for (int nf = 0; nf < 4; ++nf) {
            float m0 = mns[cb + nf * 8], m1 = mns[cb + nf * 8 + 1];
            rm[0] = fminf(rm[0], fminf(fmaf(-2.f, acc[0][nf][0], m0), fmaf(-2.f, acc[0][nf][1], m1)));
            rm[1] = fminf(rm[1], fminf(fmaf(-2.f, acc[0][nf][2], m0), fmaf(-2.f, acc[0][nf][3], m1)));
            rm[2] = fminf(rm[2], fminf(fmaf(-2.f, acc[1][nf][0], m0), fmaf(-2.f, acc[1][nf][1], m1)));
            rm[3] = fminf(rm[3], fminf(fmaf(-2.f, acc[1][nf][2], m0), fmaf(-2.f, acc[1][nf][3], m1)));
        }

        if (c < 6) {
            __syncthreads();                    // all warps done reading buffer (c&1)
            cp_chunk(c + 2, (c & 1) ? SB1 : SB0);
        }
    }

    // combine 4 lanes sharing each row
    #pragma unroll
    for (int o = 1; o < 4; o <<= 1) {
        #pragma unroll
        for (int i = 0; i < 4; ++i) rm[i] = fminf(rm[i], __shfl_xor_sync(0xffffffffu, rm[i], o));
    }
    if ((ln & 3) == 0) {
        float* rmin = (float*)(sm + SRMIN) + (w >> 3) * 256;   // per n-group array
        int r = wm + (ln >> 2);
        rmin[r] = rm[0]; rmin[r + 8] = rm[1]; rmin[r + 16] = rm[2]; rmin[r + 24] = rm[3];
    }
    __syncthreads();

    if (tid < 256) {
        const float* r0 = (const float*)(sm + SRMIN);
        double s = (double)fminf(r0[tid], r0[tid + 256]);
        #pragma unroll
        for (int o = 16; o; o >>= 1) s += __shfl_down_sync(0xffffffffu, s, o);
        if (!ln) ((double*)(sm + SRED + 64))[w] = s;
    }
    __syncthreads();

    if (tid == 0) {
        const double* dr = (const double*)(sm + SRED + 64);
        double ms = 0.0;
        #pragma unroll
        for (int i = 0; i < 8; ++i) ms += dr[i];
        atomicAdd(&g_acc[1], ms);
        const float* ws = (const float*)(sm + SRED);
        double hs = 0.0;
        #pragma unroll
        for (int i = 0; i < 16; ++i) hs += (double)ws[i];
        atomicAdd(&g_acc[3], hs);

        __threadfence();
        unsigned old = atomicAdd(&g_ticket, 1u);
        if (old == gridDim.x - 1) {
            __threadfence();
            double a0 = *(volatile double*)&g_acc[0];
            double a1 = *(volatile double*)&g_acc[1];
            double a2 = *(volatile double*)&g_acc[2];
            double a3 = *(volatile double*)&g_acc[3];
            double mem = 2.0 * (a3 + a1) / (double)((size_t)Bn * Dn * Tn);
            out[0] = (float)(a0 / (double)N_REC + 0.25 * mem - 0.1 * a2 / (double)N_DHAT);
            g_acc[0] = 0.0; g_acc[1] = 0.0; g_acc[2] = 0.0; g_acc[3] = 0.0;
            g_ticket = 0u;
            __threadfence();
        }
    }
}

extern "C" void kernel_launch(void* const* d_in, const int* in_sizes, int n_in,
                              void* d_out, int out_size) {
    (void)in_sizes; (void)n_in; (void)out_size;
    const float* Xhat = (const float*)d_in[0];
    const float* X    = (const float*)d_in[1];
    const float* H    = (const float*)d_in[2];
    const float* M    = (const float*)d_in[3];
    const float* Dh   = (const float*)d_in[4];

    cudaFuncSetAttribute(k_mma, cudaFuncAttributeMaxDynamicSharedMemorySize, SMEMT);

    k_prep<<<290, 256>>>(M, Xhat, X, Dh);
    k_mma<<<128, 512, SMEMT>>>(H, (float*)d_out);
}

// round 7
// speedup vs baseline: 8.5427x; 1.0263x over previous
#include <cuda_runtime.h>
#include <cuda_bf16.h>
#include <cstdint>

// EDMLoss = mean((Xhat-X)^2) + 0.25*memloss - 0.1*mean(Dhat)
// memloss = 2*(sum||h||^2 + sum_row min_k(||m_k||^2 - 2 h.m_k)) / (B*D*T)
// GEMM [32768x256]@[256x512] via mma.sync bf16.
// 128 CTAs x 256 threads (8 warps); CTA tile 256 rows x 512 cols;
// warp tile 64x32 per chunk (high per-warp ILP, ~255 regs/thread).

namespace {
constexpr int Bn = 64, Dn = 256, Tn = 512, Kn = 512;
constexpr int N_REC  = 64 * 8 * 512;
constexpr int N_DHAT = 64 * 512;

constexpr uint32_t AP    = 528;                 // A pitch bytes (256 bf16 + 16 pad)
constexpr uint32_t BP    = 144;                 // B pitch bytes (64 bf16 + 16 pad)
constexpr uint32_t SA    = 0;                   // A: 256*528 = 135168
constexpr uint32_t SB0   = 135168;              // B buf0: 256*144 = 36864
constexpr uint32_t SB1   = 172032;              // B buf1
constexpr uint32_t SMNS  = 208896;              // 512 f32 ||m||^2
constexpr uint32_t SRMIN = 210944;              // 2 groups * 256 f32 row mins
constexpr uint32_t SRED  = 212992;              // 8 f32 | 8 doubles at +64
constexpr uint32_t SMEMT = 213120;
}

__device__ double g_acc[4];      // 0 rec, 1 minscore, 2 dhat, 3 sum H^2 (zero-invariant)
__device__ unsigned g_ticket;
__device__ float  g_mnorm[Kn];
__device__ __align__(16) __nv_bfloat16 g_Mc[(size_t)Dn * Kn];

__device__ __forceinline__ uint32_t smem_u32(const void* p) {
    uint32_t a;
    asm("{ .reg .u64 t; cvta.to.shared.u64 t, %1; cvt.u32.u64 %0, t; }" : "=r"(a) : "l"(p));
    return a;
}
__device__ __forceinline__ void ldsm4t(uint32_t* r, uint32_t addr) {
    asm volatile("ldmatrix.sync.aligned.m8n8.x4.trans.shared.b16 {%0,%1,%2,%3}, [%4];"
                 : "=r"(r[0]), "=r"(r[1]), "=r"(r[2]), "=r"(r[3]) : "r"(addr));
}
__device__ __forceinline__ void mma16816(float* c, const uint32_t* a, const uint32_t* b) {
    asm volatile("mma.sync.aligned.m16n8k16.row.col.f32.bf16.bf16.f32 "
                 "{%0,%1,%2,%3}, {%4,%5,%6,%7}, {%8,%9}, {%0,%1,%2,%3};"
                 : "+f"(c[0]), "+f"(c[1]), "+f"(c[2]), "+f"(c[3])
                 : "r"(a[0]), "r"(a[1]), "r"(a[2]), "r"(a[3]), "r"(b[0]), "r"(b[1]));
}

// ---- prep: M convert + mnorm (blocks 0-1), rec (2-257), dhat (258-289) ----
__global__ __launch_bounds__(256) void k_prep(const float* __restrict__ M,
                                              const float* __restrict__ Xhat,
                                              const float* __restrict__ X,
                                              const float* __restrict__ Dh) {
    const int blk = blockIdx.x;
    if (blk < 2) {
        int k = blk * 256 + threadIdx.x;
        float s = 0.f;
        #pragma unroll 8
        for (int d = 0; d < Dn; ++d) {
            float v = M[(size_t)d * Kn + k];
            g_Mc[(size_t)d * Kn + k] = __float2bfloat16(v);
            s = fmaf(v, v, s);
        }
        g_mnorm[k] = s;
        return;
    }
    int which, n, b0, nb;
    const float* a; const float* bp;
    if (blk < 258) { which = 0; a = Xhat; bp = X; n = N_REC;  b0 = 2;   nb = 256; }
    else           { which = 2; a = Dh;   bp = 0; n = N_DHAT; b0 = 258; nb = 32;  }
    float s = 0.f;
    for (int i = (blk - b0) * 256 + threadIdx.x; i < n; i += nb * 256) {
        if (which == 0) { float d = a[i] - bp[i]; s = fmaf(d, d, s); }
        else            { s += a[i]; }
    }
    #pragma unroll
    for (int o = 16; o; o >>= 1) s += __shfl_down_sync(0xffffffffu, s, o);
    __shared__ float ws[8];
    int lane = threadIdx.x & 31, w = threadIdx.x >> 5;
    if (!lane) ws[w] = s;
    __syncthreads();
    if (threadIdx.x == 0) {
        float t = 0.f;
        #pragma unroll
        for (int i = 0; i < 8; ++i) t += ws[i];
        atomicAdd(&g_acc[which], (double)t);
    }
}

// ---- main GEMM + min epilogue: 256 rows x 512 cols per CTA, 256 threads ----
__global__ __launch_bounds__(256, 1) void k_mma(const float* __restrict__ H, float* out) {
    extern __shared__ char sm[];
    const uint32_t sb = smem_u32(sm);
    const int tid = threadIdx.x, w = tid >> 5, ln = tid & 31;
    const int row0 = blockIdx.x * 256;
    const int b = row0 >> 9, t0 = row0 & 511;          // t0 in {0, 256}

    ((float*)(sm + SMNS))[tid]       = g_mnorm[tid];
    ((float*)(sm + SMNS))[tid + 256] = g_mnorm[tid + 256];

    const size_t gmc = __cvta_generic_to_global((const void*)g_Mc);
    auto cp_chunk = [&](int c, uint32_t dstoff) {       // 64-col chunk: 256 rows * 128B
        #pragma unroll
        for (int i = 0; i < 8; ++i) {
            int u = tid + 256 * i;                      // 0..2047 16B units
            int d = u >> 3, seg = u & 7;
            uint32_t dst = sb + dstoff + d * BP + seg * 16;
            size_t   src = gmc + (size_t)d * 1024 + (size_t)c * 128 + seg * 16;
            asm volatile("cp.async.cg.shared.global [%0], [%1], 16;" :: "r"(dst), "l"(src));
        }
        asm volatile("cp.async.commit_group;" ::: "memory");
    };
    cp_chunk(0, SB0);
    cp_chunk(1, SB1);

    // Stage A: H[b][d][t0..t0+255] fp32 -> bf16 smem [d][t]; accumulate sum(H^2).
    float sq = 0.f;
    const float* Hp = H + (size_t)b * Dn * Tn + t0;
    #pragma unroll
    for (int i = 0; i < 64; ++i) {
        int u = tid + 256 * i;                 // 0..16383 float4 units
        int d = u >> 6, seg = u & 63;          // 64 float4 per row
        float4 v = *(const float4*)(Hp + (size_t)d * Tn + seg * 4);
        sq = fmaf(v.x, v.x, fmaf(v.y, v.y, fmaf(v.z, v.z, fmaf(v.w, v.w, sq))));
        __nv_bfloat162 p0 = __floats2bfloat162_rn(v.x, v.y);
        __nv_bfloat162 p1 = __floats2bfloat162_rn(v.z, v.w);
        uint32_t a = sb + SA + d * AP + seg * 8;
        asm volatile("st.shared.v2.b32 [%0], {%1,%2};"
                     :: "r"(a), "r"(*(uint32_t*)&p0), "r"(*(uint32_t*)&p1) : "memory");
    }
    #pragma unroll
    for (int o = 16; o; o >>= 1) sq += __shfl_down_sync(0xffffffffu, sq, o);
    if (!ln) ((float*)(sm + SRED))[w] = sq;

    // 8 warps: 4 (m) x 2 (n). Warp tile per chunk: 64 rows x 32 cols.
    const int wm  = (w & 3) * 64;
    const int wn  = (w >> 2) * 32;
    const int s1  = ((ln >> 3) & 1) * 8;
    const int s2  = (ln >> 4) * 8;
    const int r8  = ln & 7;
    const float* mns = (const float*)(sm + SMNS);

    float rm[8];
    #pragma unroll
    for (int i = 0; i < 8; ++i) rm[i] = 3.4e38f;

    for (int c = 0; c < 8; ++c) {
        asm volatile("cp.async.wait_group 1;" ::: "memory");   // chunk c resident
        __syncthreads();
        const uint32_t bb = sb + ((c & 1) ? SB1 : SB0);

        float acc[4][4][4];
        #pragma unroll
        for (int mf = 0; mf < 4; ++mf)
            #pragma unroll
            for (int nf = 0; nf < 4; ++nf)
                #pragma unroll
                for (int j = 0; j < 4; ++j) acc[mf][nf][j] = 0.f;

        #pragma unroll
        for (int ks = 0; ks < 16; ++ks) {
            const int d0 = ks * 16;
            uint32_t af[4][4], bf[2][4];
            #pragma unroll
            for (int np = 0; np < 2; ++np)
                ldsm4t(bf[np], bb + (d0 + s1 + r8) * BP + (wn + np * 16 + s2) * 2);
            #pragma unroll
            for (int mf = 0; mf < 4; ++mf)
                ldsm4t(af[mf], sb + SA + (d0 + s2 + r8) * AP + (wm + mf * 16 + s1) * 2);
            #pragma unroll
            for (int mf = 0; mf < 4; ++mf)
                #pragma unroll
                for (int nf = 0; nf < 4; ++nf)
                    mma16816(acc[mf][nf], af[mf], &bf[nf >> 1][(nf & 1) * 2]);
        }

        // epilogue: score = ||m||^2 - 2*dot, running min per row
        const int cb = c * 64 + wn + 2 * (ln & 3);
        #pragma unroll
        for (int nf = 0; nf < 4; ++nf) {
            float m0 = mns[cb + nf * 8], m1 = mns[cb + nf * 8 + 1];
            #pragma unroll
            for (int mf = 0; mf < 4; ++mf) {
                rm[mf * 2]     = fminf(rm[mf * 2],
                    fminf(fmaf(-2.f, acc[mf][nf][0], m0), fmaf(-2.f, acc[mf][nf][1], m1)));
                rm[mf * 2 + 1] = fminf(rm[mf * 2 + 1],
                    fminf(fmaf(-2.f, acc[mf][nf][2], m0), fmaf(-2.f, acc[mf][nf][3], m1)));
            }
        }

        if (c < 6) {
            __syncthreads();                    // all warps done reading buffer (c&1)
            cp_chunk(c + 2, (c & 1) ? SB1 : SB0);
        }
    }

    // combine 4 lanes sharing each row
    #pragma unroll
    for (int o = 1; o < 4; o <<= 1) {
        #pragma unroll
        for (int i = 0; i < 8; ++i) rm[i] = fminf(rm[i], __shfl_xor_sync(0xffffffffu, rm[i], o));
    }
    if ((ln & 3) == 0) {
        float* rmin = (float*)(sm + SRMIN) + (w >> 2) * 256;   // per n-group array
        int r = wm + (ln >> 2);
        #pragma unroll
        for (int mf = 0; mf < 4; ++mf) {
            rmin[r + mf * 16]     = rm[mf * 2];
            rmin[r + mf * 16 + 8] = rm[mf * 2 + 1];
        }
    }
    __syncthreads();

    {   // all 256 threads: combine n-groups, sum rows
        const float* r0 = (const float*)(sm + SRMIN);
        double s = (double)fminf(r0[tid], r0[tid + 256]);
        #pragma unroll
        for (int o = 16; o; o >>= 1) s += __shfl_down_sync(0xffffffffu, s, o);
        if (!ln) ((double*)(sm + SRED + 64))[w] = s;
    }
    __syncthreads();

    if (tid == 0) {
        const double* dr = (const double*)(sm + SRED + 64);
        double ms = 0.0;
        #pragma unroll
        for (int i = 0; i < 8; ++i) ms += dr[i];
        atomicAdd(&g_acc[1], ms);
        const float* ws = (const float*)(sm + SRED);
        double hs = 0.0;
        #pragma unroll
        for (int i = 0; i < 8; ++i) hs += (double)ws[i];
        atomicAdd(&g_acc[3], hs);

        __threadfence();
        unsigned old = atomicAdd(&g_ticket, 1u);
        if (old == gridDim.x - 1) {
            __threadfence();
            double a0 = *(volatile double*)&g_acc[0];
            double a1 = *(volatile double*)&g_acc[1];
            double a2 = *(volatile double*)&g_acc[2];
            double a3 = *(volatile double*)&g_acc[3];
            double mem = 2.0 * (a3 + a1) / (double)((size_t)Bn * Dn * Tn);
            out[0] = (float)(a0 / (double)N_REC + 0.25 * mem - 0.1 * a2 / (double)N_DHAT);
            g_acc[0] = 0.0; g_acc[1] = 0.0; g_acc[2] = 0.0; g_acc[3] = 0.0;
            g_ticket = 0u;
            __threadfence();
        }
    }
}

extern "C" void kernel_launch(void* const* d_in, const int* in_sizes, int n_in,
                              void* d_out, int out_size) {
    (void)in_sizes; (void)n_in; (void)out_size;
    const float* Xhat = (const float*)d_in[0];
    const float* X    = (const float*)d_in[1];
    const float* H    = (const float*)d_in[2];
    const float* M    = (const float*)d_in[3];
    const float* Dh   = (const float*)d_in[4];

    cudaFuncSetAttribute(k_mma, cudaFuncAttributeMaxDynamicSharedMemorySize, SMEMT);

    k_prep<<<290, 256>>>(M, Xhat, X, Dh);
    k_mma<<<128, 256, SMEMT>>>(H, (float*)d_out);
}